// round 1
// baseline (speedup 1.0000x reference)
#include <cuda_runtime.h>
#include <math.h>

// Problem constants (fixed by the dataset)
#define BB     8
#define T_MAX  256
#define U_MAX  128
#define U1     129          // U_MAX + 1
#define VV     512
#define NEG_INF (-1e30f)

// Scratch (device globals: no allocation allowed in kernel_launch)
__device__ float g_blank[BB * T_MAX * U1];     // log P(blank | b,t,u)
__device__ float g_emit [BB * T_MAX * U_MAX];  // log P(y[b,u] | b,t,u)
__device__ float g_res  [BB];                  // per-batch log-prob

// ---------------------------------------------------------------------------
// Phase 1: one warp per (b,t,u) row. Log-softmax over V=512, extract the
// blank and emit log-probs. 541 MB read, 2 MB written. HBM-bound.
// ---------------------------------------------------------------------------
__global__ void __launch_bounds__(256) lse_kernel(const float* __restrict__ logits,
                                                  const int*   __restrict__ y)
{
    const int warp = (blockIdx.x * blockDim.x + threadIdx.x) >> 5;
    const int lane = threadIdx.x & 31;
    const int NROWS = BB * T_MAX * U1;
    if (warp >= NROWS) return;

    const float4* p = (const float4*)(logits + (size_t)warp * VV);
    // 4 x float4 per lane covers 128 float4 = 512 floats, fully coalesced.
    float4 v0 = p[lane];
    float4 v1 = p[lane + 32];
    float4 v2 = p[lane + 64];
    float4 v3 = p[lane + 96];

    float m = fmaxf(fmaxf(fmaxf(v0.x, v0.y), fmaxf(v0.z, v0.w)),
                    fmaxf(fmaxf(v1.x, v1.y), fmaxf(v1.z, v1.w)));
    m = fmaxf(m, fmaxf(fmaxf(fmaxf(v2.x, v2.y), fmaxf(v2.z, v2.w)),
                       fmaxf(fmaxf(v3.x, v3.y), fmaxf(v3.z, v3.w))));
    #pragma unroll
    for (int off = 16; off; off >>= 1)
        m = fmaxf(m, __shfl_xor_sync(0xFFFFFFFFu, m, off));

    float s = expf(v0.x - m) + expf(v0.y - m) + expf(v0.z - m) + expf(v0.w - m)
            + expf(v1.x - m) + expf(v1.y - m) + expf(v1.z - m) + expf(v1.w - m)
            + expf(v2.x - m) + expf(v2.y - m) + expf(v2.z - m) + expf(v2.w - m)
            + expf(v3.x - m) + expf(v3.y - m) + expf(v3.z - m) + expf(v3.w - m);
    #pragma unroll
    for (int off = 16; off; off >>= 1)
        s += __shfl_xor_sync(0xFFFFFFFFu, s, off);

    if (lane == 0) {
        const float lse = m + logf(s);
        const int u  = warp % U1;
        const int bt = warp / U1;          // = b*T_MAX + t
        // lane 0's v0.x is element 0 of the row == blank logit
        g_blank[warp] = v0.x - lse;
        if (u < U_MAX) {
            const int b  = bt / T_MAX;
            const int yv = y[b * U_MAX + u];            // in [1, V)
            const float ly = logits[(size_t)warp * VV + yv]; // L1 hit (row just read)
            g_emit[bt * U_MAX + u] = ly - lse;
        }
    }
}

// ---------------------------------------------------------------------------
// Phase 2: anti-diagonal wavefront DP, one CTA per batch, thread = u.
// alpha[t][u] = logaddexp(alpha[t-1][u] + blank[t-1][u],
//                         alpha[t][u-1] + emit [t][u-1])
// Double-buffered shared row -> 1 barrier per diagonal. Loads for the next
// diagonal are issued before the barrier (addresses data-independent).
// ---------------------------------------------------------------------------
__global__ void __launch_bounds__(U1) alpha_kernel(const int* __restrict__ T_len,
                                                   const int* __restrict__ U_len)
{
    const int b = blockIdx.x;
    const int u = threadIdx.x;             // 0..128
    const int Tl = T_len[b];
    const int Ul = U_len[b];

    const float* __restrict__ blank = g_blank + b * T_MAX * U1;
    const float* __restrict__ emit  = g_emit  + b * T_MAX * U_MAX;

    __shared__ float sh[2][U1];

    float myalpha = NEG_INF;               // alpha[t-1][u] along my column
    float bl_nxt = 0.f, em_nxt = 0.f;      // prefetched operands for diagonal d

    // d=0 only touches (t=0,u=0) which needs no operands; prefetch starts at d=1.
    for (int d = 0; d < T_MAX + U_MAX; ++d) {
        const float bl = bl_nxt;
        const float em = em_nxt;

        // prefetch operands for diagonal d+1 (t2 = d+1-u)
        {
            const int t2 = d + 1 - u;
            if (t2 >= 1 && t2 < T_MAX) bl_nxt = blank[(t2 - 1) * U1 + u];
            if (u >= 1 && t2 >= 0 && t2 < T_MAX) em_nxt = emit[t2 * U_MAX + (u - 1)];
        }

        const int t = d - u;
        if (t >= 0 && t < T_MAX) {
            const float left = (u > 0) ? sh[(d + 1) & 1][u - 1] : NEG_INF; // alpha[t][u-1]
            float nv;
            if (t == 0 && u == 0) {
                nv = 0.f;
            } else {
                const float vert = (t >= 1) ? (myalpha + bl) : NEG_INF;
                const float horz = (u >= 1) ? (left + em)    : NEG_INF;
                const float mx = fmaxf(vert, horz);
                nv = mx + log1pf(expf(fminf(vert, horz) - mx));
            }
            myalpha = nv;
            sh[d & 1][u] = nv;
            if (t == Tl - 1 && u == Ul)
                g_res[b] = nv + blank[t * U1 + u];
        }
        __syncthreads();
    }
}

// ---------------------------------------------------------------------------
// Phase 3: loss = -mean_b(log_prob[b])
// ---------------------------------------------------------------------------
__global__ void finalize_kernel(float* __restrict__ out)
{
    if (threadIdx.x == 0) {
        float s = 0.f;
        #pragma unroll
        for (int b = 0; b < BB; ++b) s += g_res[b];
        out[0] = -s / (float)BB;
    }
}

extern "C" void kernel_launch(void* const* d_in, const int* in_sizes, int n_in,
                              void* d_out, int out_size)
{
    const float* logits = (const float*)d_in[0];
    const int*   y      = (const int*)  d_in[1];
    const int*   T_len  = (const int*)  d_in[2];
    const int*   U_len  = (const int*)  d_in[3];

    const int rows = BB * T_MAX * U1;          // 264192 warps
    const int warps_per_block = 256 / 32;
    const int nblocks = (rows + warps_per_block - 1) / warps_per_block;

    lse_kernel<<<nblocks, 256>>>(logits, y);
    alpha_kernel<<<BB, U1>>>(T_len, U_len);
    finalize_kernel<<<1, 32>>>((float*)d_out);
}

// round 2
// speedup vs baseline: 2.0213x; 2.0213x over previous
#include <cuda_runtime.h>
#include <math.h>

// Problem constants (fixed by the dataset)
#define BB     8
#define T_MAX  256
#define U_MAX  128
#define U1     129          // U_MAX + 1
#define VV     512
#define NEG_INF (-1e30f)
#define NDIAG  (T_MAX + U_MAX)   // 384, divisible by 4

// Scratch (device globals: no allocation allowed in kernel_launch)
__device__ float g_blank[BB * T_MAX * U1];     // log P(blank | b,t,u)
__device__ float g_emit [BB * T_MAX * U_MAX];  // log P(y[b,u] | b,t,u)
__device__ float g_res  [BB];                  // per-batch log-prob

// ---------------------------------------------------------------------------
// Phase 1: one warp per (b,t,u) row. Log-softmax over V=512, extract the
// blank and emit log-probs. 541 MB read, 2 MB written. HBM-bound.
// ---------------------------------------------------------------------------
__global__ void __launch_bounds__(256) lse_kernel(const float* __restrict__ logits,
                                                  const int*   __restrict__ y)
{
    const int warp = (blockIdx.x * blockDim.x + threadIdx.x) >> 5;
    const int lane = threadIdx.x & 31;
    const int NROWS = BB * T_MAX * U1;
    if (warp >= NROWS) return;

    const float4* p = (const float4*)(logits + (size_t)warp * VV);
    // 4 x float4 per lane covers 128 float4 = 512 floats, fully coalesced.
    float4 v0 = p[lane];
    float4 v1 = p[lane + 32];
    float4 v2 = p[lane + 64];
    float4 v3 = p[lane + 96];

    float m = fmaxf(fmaxf(fmaxf(v0.x, v0.y), fmaxf(v0.z, v0.w)),
                    fmaxf(fmaxf(v1.x, v1.y), fmaxf(v1.z, v1.w)));
    m = fmaxf(m, fmaxf(fmaxf(fmaxf(v2.x, v2.y), fmaxf(v2.z, v2.w)),
                       fmaxf(fmaxf(v3.x, v3.y), fmaxf(v3.z, v3.w))));
    #pragma unroll
    for (int off = 16; off; off >>= 1)
        m = fmaxf(m, __shfl_xor_sync(0xFFFFFFFFu, m, off));

    float s = __expf(v0.x - m) + __expf(v0.y - m) + __expf(v0.z - m) + __expf(v0.w - m)
            + __expf(v1.x - m) + __expf(v1.y - m) + __expf(v1.z - m) + __expf(v1.w - m)
            + __expf(v2.x - m) + __expf(v2.y - m) + __expf(v2.z - m) + __expf(v2.w - m)
            + __expf(v3.x - m) + __expf(v3.y - m) + __expf(v3.z - m) + __expf(v3.w - m);
    #pragma unroll
    for (int off = 16; off; off >>= 1)
        s += __shfl_xor_sync(0xFFFFFFFFu, s, off);

    if (lane == 0) {
        const float lse = m + __logf(s);
        const int u  = warp % U1;
        const int bt = warp / U1;          // = b*T_MAX + t
        // lane 0's v0.x is element 0 of the row == blank logit
        g_blank[warp] = v0.x - lse;
        if (u < U_MAX) {
            const int b  = bt / T_MAX;
            const int yv = y[b * U_MAX + u];            // in [1, V)
            const float ly = logits[(size_t)warp * VV + yv]; // L1 hit (row just read)
            g_emit[bt * U_MAX + u] = ly - lse;
        }
    }
}

// ---------------------------------------------------------------------------
// Phase 2: anti-diagonal wavefront DP, one CTA per batch, thread = u.
// alpha[t][u] = logaddexp(alpha[t-1][u] + blank[t-1][u],
//                         alpha[t][u-1] + emit [t][u-1])
// Left operand via __shfl_up (intra-warp); shared mem only at warp
// boundaries. Blank/emit operands flow through a depth-4 register prefetch
// pipeline so L2 latency (~250-380cyc) is covered by 4 iterations of work.
// One __syncthreads per diagonal.
// ---------------------------------------------------------------------------
#define ALPHA_THREADS 160   // 5 full warps; u = 0..128 active, rest barrier-only

__global__ void __launch_bounds__(ALPHA_THREADS)
alpha_kernel(const int* __restrict__ T_len, const int* __restrict__ U_len)
{
    const int b    = blockIdx.x;
    const int u    = threadIdx.x;
    const int lane = u & 31;
    const int wrp  = u >> 5;
    const int Tl   = T_len[b];
    const int Ul   = U_len[b];
    const bool au  = (u < U1);

    const float* __restrict__ blank = g_blank + b * T_MAX * U1;
    const float* __restrict__ emit  = g_emit  + b * T_MAX * U_MAX;

    __shared__ float sh[2][5];   // warp-boundary alpha, double buffered by parity

    float myalpha = NEG_INF;

    // operand loader for diagonal d (t = d - u):
    //   bl = blank[(t-1)*U1 + u]   (needs t in [1, T_MAX))
    //   em = emit [ t*U_MAX + u-1] (needs u>=1, t in [0, T_MAX))
    #define LOADOPS(d, bl, em)                                             \
        {                                                                  \
            const int t_ = (d) - u;                                        \
            (bl) = 0.f; (em) = 0.f;                                        \
            if (au && t_ >= 1 && t_ < T_MAX) (bl) = blank[(t_-1)*U1 + u];  \
            if (au && u >= 1 && t_ >= 0 && t_ < T_MAX) (em) = emit[t_*U_MAX + (u-1)]; \
        }

    float blq[4], emq[4];
    #pragma unroll
    for (int k = 0; k < 4; ++k) LOADOPS(k, blq[k], emq[k]);

    for (int d0 = 0; d0 < NDIAG; d0 += 4) {
        float blc[4], emc[4];
        #pragma unroll
        for (int k = 0; k < 4; ++k) { blc[k] = blq[k]; emc[k] = emq[k]; }
        // issue next group's loads now; consumed ~4 diagonals later
        #pragma unroll
        for (int k = 0; k < 4; ++k) LOADOPS(d0 + 4 + k, blq[k], emq[k]);

        #pragma unroll
        for (int k = 0; k < 4; ++k) {
            const int d = d0 + k;
            // left = alpha[t][u-1], computed by thread u-1 on diagonal d-1
            float left = __shfl_up_sync(0xFFFFFFFFu, myalpha, 1);
            if (lane == 0) left = (wrp > 0) ? sh[(d + 1) & 1][wrp - 1] : NEG_INF;

            const int t = d - u;
            if (au && t >= 0 && t < T_MAX) {
                float nv;
                if (d == 0) {                 // only cell (0,0) lives on diag 0
                    nv = 0.f;
                } else {
                    const float vert = (t >= 1) ? (myalpha + blc[k]) : NEG_INF;
                    const float horz = (u >= 1) ? (left    + emc[k]) : NEG_INF;
                    const float mx = fmaxf(vert, horz);
                    const float mn = fminf(vert, horz);
                    nv = mx + __logf(1.0f + __expf(mn - mx));
                }
                myalpha = nv;
                if (t == Tl - 1 && u == Ul)
                    g_res[b] = nv + blank[t * U1 + u];
            }
            if (lane == 31) sh[d & 1][wrp] = myalpha;
            __syncthreads();
        }
    }
    #undef LOADOPS
}

// ---------------------------------------------------------------------------
// Phase 3: loss = -mean_b(log_prob[b])
// ---------------------------------------------------------------------------
__global__ void finalize_kernel(float* __restrict__ out)
{
    if (threadIdx.x == 0) {
        float s = 0.f;
        #pragma unroll
        for (int b = 0; b < BB; ++b) s += g_res[b];
        out[0] = -s / (float)BB;
    }
}

extern "C" void kernel_launch(void* const* d_in, const int* in_sizes, int n_in,
                              void* d_out, int out_size)
{
    const float* logits = (const float*)d_in[0];
    const int*   y      = (const int*)  d_in[1];
    const int*   T_len  = (const int*)  d_in[2];
    const int*   U_len  = (const int*)  d_in[3];

    const int rows = BB * T_MAX * U1;          // 264192 warps
    const int warps_per_block = 256 / 32;
    const int nblocks = (rows + warps_per_block - 1) / warps_per_block;

    lse_kernel<<<nblocks, 256>>>(logits, y);
    alpha_kernel<<<BB, ALPHA_THREADS>>>(T_len, U_len);
    finalize_kernel<<<1, 32>>>((float*)d_out);
}